// round 4
// baseline (speedup 1.0000x reference)
#include <cuda_runtime.h>
#include <cuda_bf16.h>
#include <cstdint>

// Scratch (device globals — no allocations allowed).
#define RED_BLOCKS 1184
__device__ unsigned g_partial[RED_BLOCKS];
__device__ unsigned g_maxabs;

// ---------------------------------------------------------------------------
// Robust small-integer scalar decode (int32/int64/float32/float64).
// ---------------------------------------------------------------------------
__device__ __forceinline__ int decode_scalar(const int* p, int dflt) {
    if (p == nullptr) return dflt;
    int w0 = p[0];
    if (w0 >= -1000000 && w0 <= 1000000) {
        if (w0 != 0) return w0;                 // int32 / int64 small value
        int w1 = p[1];
        if (w1 == 0) return 0;
        double d = __hiloint2double(w1, w0);    // float64 candidate
        if (d >= -1e6 && d <= 1e6) return (int)d;
        return 0;
    }
    float f = __int_as_float(w0);               // float32 candidate
    if (f >= -1e6f && f <= 1e6f) return (int)f;
    int w1 = p[1];
    double d = __hiloint2double(w1, w0);
    if (d >= -1e6 && d <= 1e6) return (int)d;
    return dflt;
}

// ---------------------------------------------------------------------------
// Kernel 1: per-block max|grad| -> g_partial[block]. No atomics, no reset.
// ---------------------------------------------------------------------------
__global__ void uw_reduce_kernel(const int4* __restrict__ g, long n4) {
    unsigned m = 0u;
    long idx = (long)blockIdx.x * blockDim.x + threadIdx.x;
    long stride = (long)gridDim.x * blockDim.x;
    for (long i = idx; i < n4; i += stride) {
        int4 v = __ldg(&g[i]);
        unsigned a0 = (unsigned)(v.x < 0 ? -v.x : v.x);
        unsigned a1 = (unsigned)(v.y < 0 ? -v.y : v.y);
        unsigned a2 = (unsigned)(v.z < 0 ? -v.z : v.z);
        unsigned a3 = (unsigned)(v.w < 0 ? -v.w : v.w);
        m = max(m, max(max(a0, a1), max(a2, a3)));
    }
    m = __reduce_max_sync(0xffffffffu, m);
    __shared__ unsigned smax[32];
    int lane = threadIdx.x & 31;
    int wid  = threadIdx.x >> 5;
    if (lane == 0) smax[wid] = m;
    __syncthreads();
    if (wid == 0) {
        int nwarps = (blockDim.x + 31) >> 5;
        unsigned v = (lane < nwarps) ? smax[lane] : 0u;
        v = __reduce_max_sync(0xffffffffu, v);
        if (lane == 0) g_partial[blockIdx.x] = v;
    }
}

// ---------------------------------------------------------------------------
// Kernel 2: reduce partials -> g_maxabs (single block, plain store).
// ---------------------------------------------------------------------------
__global__ void uw_final_kernel() {
    unsigned m = 0u;
    for (int i = threadIdx.x; i < RED_BLOCKS; i += blockDim.x)
        m = max(m, g_partial[i]);
    m = __reduce_max_sync(0xffffffffu, m);
    __shared__ unsigned smax[32];
    int lane = threadIdx.x & 31;
    int wid  = threadIdx.x >> 5;
    if (lane == 0) smax[wid] = m;
    __syncthreads();
    if (wid == 0) {
        int nwarps = (blockDim.x + 31) >> 5;
        unsigned v = (lane < nwarps) ? smax[lane] : 0u;
        v = __reduce_max_sync(0xffffffffu, v);
        if (lane == 0) g_maxabs = v;
    }
}

// ---------------------------------------------------------------------------
// Pseudo-stochastic shift quantizer (faithful _psto_shift, s >= 1).
// ---------------------------------------------------------------------------
__device__ __forceinline__ int uw_psto(int x, int s) {
    int rt   = x >> s;                 // floor(x / 2^s)
    int prob = x & ((1 << s) - 1);     // non-negative floor remainder
    int hs   = s >> 1;
    int qprob = prob >> hs;
    int prn   = (prob & ((1 << hs) - 1)) * (1 + (s & 1));
    int sgn   = (x > 0) - (x < 0);
    int dec   = (qprob <= prn) ? 0 : sgn;
    int gv    = rt + dec;
    return min(127, max(-127, gv));
}

// ---------------------------------------------------------------------------
// Kernel 3: elementwise update. One thread = 4 elements.
//   weight as int4 (int32 input!), grad as int4, outputs as float4 stores.
// ---------------------------------------------------------------------------
__global__ void uw_update_kernel(
    const int4* __restrict__ w4,   // weight promoted to int32 by harness
    const int4* __restrict__ g4,
    const int*  __restrict__ p_err_exp,
    const int*  __restrict__ p_act_in_exp,
    const int*  __restrict__ p_mu,
    float* __restrict__ out_w,
    float* __restrict__ out_g,
    float* __restrict__ out_exp,
    long n4)
{
    long i = (long)blockIdx.x * blockDim.x + threadIdx.x;

    int mu  = decode_scalar(p_mu, 7);
    unsigned rng = g_maxabs;
    int bw = (rng == 0u) ? 0
             : (int)ceilf(log2f(fmaxf((float)rng, 1.0f)));
    int shift = bw - mu;
    int s = max(shift, 1);
    bool zero_branch  = (bw == 0);
    bool trunc_branch = (shift < 1);

    if (i == 0) {
        int gs = (zero_branch || trunc_branch) ? 0 : shift;
        int ee = decode_scalar(p_err_exp, -10);
        int ae = decode_scalar(p_act_in_exp, -7);
        *out_exp = (float)(ee + gs + ae);
    }

    if (i >= n4) return;

    int4 wv = __ldg(&w4[i]);
    int4 gv = __ldg(&g4[i]);

    int gx[4] = { gv.x, gv.y, gv.z, gv.w };
    int wi[4] = { wv.x, wv.y, wv.z, wv.w };

    float og[4], ow[4];
#pragma unroll
    for (int k = 0; k < 4; k++) {
        int gq;
        if (zero_branch)       gq = 0;
        else if (trunc_branch) gq = (int)(signed char)gx[k]; // wraps like astype(int8)
        else                   gq = uw_psto(gx[k], s);
        int nw = wi[k] - gq;
        nw = min(127, max(-127, nw));
        og[k] = (float)gq;
        ow[k] = (float)nw;
    }

    ((float4*)out_w)[i] = make_float4(ow[0], ow[1], ow[2], ow[3]);
    ((float4*)out_g)[i] = make_float4(og[0], og[1], og[2], og[3]);
}

// ---------------------------------------------------------------------------
// Launch. Inputs: weight int32[N] (promoted int8), grad int32[N],
// err_exp, act_in_exp, mu (int32 scalars).
// Output: float32[2N+1] = concat(new_weight, grad, grad_exp).
// ---------------------------------------------------------------------------
extern "C" void kernel_launch(void* const* d_in, const int* in_sizes, int n_in,
                              void* d_out, int out_size)
{
    const int4* w4 = (const int4*)d_in[0];
    const int4* g4 = (const int4*)d_in[1];
    const int* p_err = (n_in > 2) ? (const int*)d_in[2] : nullptr;
    const int* p_act = (n_in > 3) ? (const int*)d_in[3] : nullptr;
    const int* p_mu  = (n_in > 4) ? (const int*)d_in[4] : nullptr;

    long N  = (long)in_sizes[0];
    long n4 = N >> 2;

    float* out   = (float*)d_out;
    float* out_w = out;
    float* out_g = out + N;
    float* out_e = out + 2 * N;

    uw_reduce_kernel<<<RED_BLOCKS, 256>>>(g4, n4);
    uw_final_kernel<<<1, 256>>>();

    long blocks = (n4 + 255) / 256;
    uw_update_kernel<<<(int)blocks, 256>>>(w4, g4, p_err, p_act, p_mu,
                                           out_w, out_g, out_e, n4);
}